// round 16
// baseline (speedup 1.0000x reference)
#include <cuda_runtime.h>
#include <cuda_fp16.h>
#include <cstdint>

typedef unsigned int u32;

#define BATCH 16384
#define LDA 280                    // fp16 elems per A row (272 used, padded)
#define LDB 280
#define TILEB (64 * LDB * 2)       // 35840 bytes per B tile
#define THREADS 512

// ---------------- device scratch (allocation-free rule) ----------------
__device__ __align__(16) __half d_Bw[4][16][64 * LDB];   // [layer][ntile][n][k]
__device__ float d_hs[(size_t)256 * BATCH];              // [unit][batch]
__device__ float d_cs[(size_t)256 * BATCH];

struct Params {
    const float* Wih[4]; const float* Whh[4];
    const float* bih[4]; const float* bhh[4];
    const float* fcsW; const float* fcsB;
    const float* fccW; const float* fccB;
    const float* embW; const float* embB;
    const float* speed; const float* pos;
    float* out;
};

// ---------------- PTX helpers (all legal on compute_103) ----------------
__device__ __forceinline__ u32 s2u(const void* p) {
    u32 a;
    asm("{ .reg .u64 t; cvta.to.shared.u64 t, %1; cvt.u32.u64 %0, t; }" : "=r"(a) : "l"(p));
    return a;
}
__device__ __forceinline__ void ldsm4(u32* r, u32 a) {
    asm volatile("ldmatrix.sync.aligned.m8n8.x4.shared.b16 {%0,%1,%2,%3}, [%4];"
                 : "=r"(r[0]), "=r"(r[1]), "=r"(r[2]), "=r"(r[3]) : "r"(a));
}
__device__ __forceinline__ void mma16816(float* c, const u32* a, const u32* b) {
    asm volatile("mma.sync.aligned.m16n8k16.row.col.f32.f16.f16.f32 "
                 "{%0,%1,%2,%3}, {%4,%5,%6,%7}, {%8,%9}, {%0,%1,%2,%3};"
                 : "+f"(c[0]), "+f"(c[1]), "+f"(c[2]), "+f"(c[3])
                 : "r"(a[0]), "r"(a[1]), "r"(a[2]), "r"(a[3]), "r"(b[0]), "r"(b[1]));
}
__device__ __forceinline__ void cp16(u32 dst, const void* src) {
    asm volatile("cp.async.cg.shared.global [%0], [%1], 16;" :: "r"(dst), "l"(src) : "memory");
}
#define CP_COMMIT() asm volatile("cp.async.commit_group;" ::: "memory")
#define CP_WAIT(n)  asm volatile("cp.async.wait_group %0;" :: "n"(n) : "memory")

__device__ __forceinline__ float tanha(float x) {
    float y; asm("tanh.approx.f32 %0, %1;" : "=f"(y) : "f"(x)); return y;
}
__device__ __forceinline__ float sigm(float x) { return fmaf(tanha(0.5f * x), 0.5f, 0.5f); }

// ---------------- prep: pack fp16 B tiles [n = 4u+g][k] ----------------
// k: 0-255 Whh, 256-259 Wih, 260 bias(ih+hh), 261-279 zero.
__global__ void prep_kernel(Params P) {
    int idx = blockIdx.x * 256 + threadIdx.x;   // one thread = 8 k values
    if (idx >= 4 * 16 * 64 * 35) return;
    int kc = idx % 35, nl = (idx / 35) & 63, nt = (idx / (35 * 64)) & 15, l = idx / (35 * 64 * 16);
    int g = nl & 3, ul = nl >> 2, u = nt * 16 + ul, row = g * 256 + u;
    int k0 = kc * 8;
    __half hv[8];
#pragma unroll
    for (int i = 0; i < 8; i++) {
        int k = k0 + i; float v = 0.f;
        if (k < 256)       v = P.Whh[l][(size_t)row * 256 + k];
        else if (k < 260)  v = P.Wih[l][row * 4 + (k - 256)];
        else if (k == 260) v = P.bih[l][row] + P.bhh[l][row];
        hv[i] = __float2half(v);
    }
    *(uint4*)(&d_Bw[l][nt][nl * LDB + k0]) = *(uint4*)hv;
}

// ---------------- one LSTM phase (16 steps, 64 rows) ----------------
// mode: 0 enc-store, 1 enc-add, 2 dec-speed, 3 dec-cross
__device__ void run_phase(int mode, const __half* __restrict__ Bl,
                          const float* __restrict__ xseq, float* __restrict__ out,
                          int b0, int tid,
                          __half* A, u32 aU, u32 bs,
                          float* shc, const float* shw, const float* sb, float* lg)
{
    const int lane = tid & 31, w = tid >> 5;
    const int m = w >> 2, p = w & 3;          // 4 m-groups x 4 n-groups
    const int R0 = 16 * m;
    const int q = lane >> 2, cc = lane & 3;
    const int hrow = (tid & 255) >> 2, hs = tid & 3;   // x/head mapping (tid<256 active)

    // ---- phase init (coalesced: u = i>>6, r = i&63) ----
    if (mode <= 1) {
        for (int i = tid; i < 64 * 256; i += THREADS) {
            int u = i >> 6, r = i & 63;
            A[r * LDA + u] = __float2half(0.f);
            shc[u * 65 + r] = 0.f;
        }
    } else {
        for (int i = tid; i < 64 * 256; i += THREADS) {
            int u = i >> 6, r = i & 63;
            A[r * LDA + u] = __float2half(d_hs[(size_t)u * BATCH + b0 + r]);
            shc[u * 65 + r] = d_cs[(size_t)u * BATCH + b0 + r];
        }
        if (tid < 256)
            A[hrow * LDA + 256 + hs] = __float2half(xseq[(size_t)(b0 + hrow) * 64 + 60 + hs]);
    }
    __syncthreads();

    for (int t = 0; t < 16; t++) {
        if (mode <= 1) {   // encoder: fresh x
            if (tid < 256)
                A[hrow * LDA + 256 + hs] = __float2half(xseq[(size_t)(b0 + hrow) * 64 + t * 4 + hs]);
            __syncthreads();
        }

        // ---- hoist A fragments for this step (16 rows x 272 k) ----
        u32 aF[17][4];
        {
            const u32 aoff = aU + (u32)((R0 + (lane & 15)) * LDA + (lane >> 4) * 8) * 2u;
#pragma unroll
            for (int kt = 0; kt < 17; kt++) ldsm4(aF[kt], aoff + kt * 32u);
        }

        // prefetch tiles 0,1 into slots 0,1
        for (int pt = 0; pt < 2; pt++) {
            const char* src = (const char*)(Bl + pt * 64 * LDB);
            for (u32 o = (u32)tid * 16u; o < TILEB; o += (u32)THREADS * 16u)
                cp16(bs + pt * TILEB + o, src + o);
            CP_COMMIT();
        }

        // ---- 16 N-tiles of 64 gates, 3-slot ring, ONE sync per tile ----
        for (int nt = 0; nt < 16; nt++) {
            if (nt == 15) { CP_WAIT(0); } else { CP_WAIT(1); }
            __syncthreads();   // tile nt data visible to all; all warps done with slot (nt-1)%3;
                               // for nt==0 this also fences the aF hoist vs in-place h writes

            if (nt + 2 < 16) {   // refill slot (nt+2)%3 == (nt-1)%3
                const char* src = (const char*)(Bl + (nt + 2) * 64 * LDB);
                u32 dst = bs + (u32)((nt + 2) % 3) * TILEB;
                for (u32 o = (u32)tid * 16u; o < TILEB; o += (u32)THREADS * 16u)
                    cp16(dst + o, src + o);
                CP_COMMIT();
            }

            // 4 independent accumulator chains (even/odd kt)
            float ae[2][4], ao[2][4];
#pragma unroll
            for (int j = 0; j < 2; j++)
#pragma unroll
                for (int e = 0; e < 4; e++) { ae[j][e] = 0.f; ao[j][e] = 0.f; }

            const u32 bslot = bs + (u32)(nt % 3) * TILEB;
            const int nr = 16 * p + (lane & 7) + ((lane >> 4) & 1) * 8;
            const u32 boff = bslot + (u32)(nr * LDB + ((lane >> 3) & 1) * 8) * 2u;

#pragma unroll
            for (int kt = 0; kt < 17; kt++) {
                u32 bF[4];
                ldsm4(bF, boff + kt * 32u);            // B: [n][k] = col-major KxN, NO trans
                if (kt & 1) {
                    mma16816(ao[0], aF[kt], bF);
                    mma16816(ao[1], aF[kt], bF + 2);
                } else {
                    mma16816(ae[0], aF[kt], bF);
                    mma16816(ae[1], aF[kt], bF + 2);
                }
            }
            float acc[2][4];
#pragma unroll
            for (int j = 0; j < 2; j++)
#pragma unroll
                for (int e = 0; e < 4; e++) acc[j][e] = ae[j][e] + ao[j][e];

            // ---- epilogue: both parities work (even: row q, odd: row q+8) ----
#pragma unroll
            for (int fj = 0; fj < 2; fj++) {
                float p0 = __shfl_xor_sync(0xFFFFFFFFu, acc[fj][0], 1);
                float p1 = __shfl_xor_sync(0xFFFFFFFFu, acc[fj][1], 1);
                float p2 = __shfl_xor_sync(0xFFFFFFFFu, acc[fj][2], 1);
                float p3 = __shfl_xor_sync(0xFFFFFFFFu, acc[fj][3], 1);
                int u = nt * 16 + 4 * p + 2 * fj + (cc >> 1);
                if ((cc & 1) == 0) {
                    // even lane holds i,f; partner values are g,o (rows q, q+8)
                    int r = R0 + q;
                    float c0 = shc[u * 65 + r];
                    float cn = sigm(acc[fj][1]) * c0 + sigm(acc[fj][0]) * tanha(p0);
                    shc[u * 65 + r] = cn;
                    A[r * LDA + u] = __float2half(sigm(p1) * tanha(cn));
                } else {
                    // odd lane holds g,o; partner values are i,f (rows q, q+8)
                    int r = R0 + q + 8;
                    float c1 = shc[u * 65 + r];
                    float cn = sigm(p3) * c1 + sigm(p2) * tanha(acc[fj][2]);
                    shc[u * 65 + r] = cn;
                    A[r * LDA + u] = __float2half(sigm(acc[fj][3]) * tanha(cn));
                }
            }
        }
        __syncthreads();   // all h for step t in A

        // ---- decoder heads (h complete in A) ----
        if (mode >= 2) {
            if (tid < 256) {
                const __half2* a2 = (const __half2*)(A + hrow * LDA);
                int widx = (mode == 2) ? hs : (hs + 4);
                const float* wr = shw + widx * 256;
                float acc0 = 0.f, acc1 = 0.f;
#pragma unroll 8
                for (int k = 0; k < 128; k++) {
                    float2 f = __half22float2(a2[k]);
                    acc0 = fmaf(f.x, wr[2 * k], acc0);
                    acc1 = fmaf(f.y, wr[2 * k + 1], acc1);
                }
                float dv = acc0 + acc1 + sb[widx];
                if (mode == 2) {
                    float v = fminf(fmaxf(dv, -100.f), 100.f);
                    out[(size_t)(b0 + hrow) * 64 + t * 4 + hs] = v;
                    A[hrow * LDA + 256 + hs] = __float2half(v);
                } else {
                    A[hrow * LDA + 256 + hs] = __float2half(fmaxf(dv, 0.f));
                    if (hs < 2) {
                        const float* wc = shw + (8 + hs) * 256;
                        float b0a = 0.f, b1a = 0.f;
#pragma unroll 8
                        for (int k = 0; k < 128; k++) {
                            float2 f = __half22float2(a2[k]);
                            b0a = fmaf(f.x, wc[2 * k], b0a);
                            b1a = fmaf(f.y, wc[2 * k + 1], b1a);
                        }
                        lg[hrow * 2 + hs] = fmaxf(b0a + b1a + sb[8 + hs], 0.f);
                    }
                }
            }
            __syncthreads();
            if (mode == 3 && tid < 256 && hs == 0) {
                float l0 = lg[hrow * 2], l1 = lg[hrow * 2 + 1];
                float mx = fmaxf(l0, l1);
                float e0 = __expf(l0 - mx), e1 = __expf(l1 - mx);
                float inv = 1.0f / (e0 + e1);
                float2 cv = make_float2(e0 * inv, e1 * inv);
                *(float2*)(out + (size_t)BATCH * 64 + (size_t)(b0 + hrow) * 32 + t * 2) = cv;
            }
            __syncthreads();
        }
    }

    // ---- encoder tail: stash final h + c, coalesced [u][batch] ----
    if (mode <= 1) {
        for (int i = tid; i < 64 * 256; i += THREADS) {
            int u = i >> 6, r = i & 63;
            float h = __half2float(A[r * LDA + u]);
            float cv = shc[u * 65 + r];
            size_t gidx = (size_t)u * BATCH + b0 + r;
            if (mode == 0) { d_hs[gidx] = h; d_cs[gidx] = cv; }
            else           { d_hs[gidx] += h; d_cs[gidx] += cv; }
        }
        __syncthreads();
    }
}

// ---------------- main kernel ----------------
// smem (bytes): B ring 0..107520 | A 107520(+35840) | c 143360(+66560)
//               shw 209920(+10240) | sb 220160(+64) | lg 220224(+512)  => 220736
__global__ void __launch_bounds__(THREADS, 1) pv_main(Params P) {
    extern __shared__ __align__(16) char sm[];
    const u32 base = s2u(sm);
    const int tid = threadIdx.x;
    const int b0 = blockIdx.x * 64;

    u32 bs = base;
    __half* A = (__half*)(sm + 107520);
    u32 aU = base + 107520;
    float* shc = (float*)(sm + 143360);
    float* shw = (float*)(sm + 209920);
    float* sb  = (float*)(sm + 220160);
    float* lg  = (float*)(sm + 220224);

    // zero A fully (pads), then set bias col 260 = 1.0
    for (int i = tid; i < 64 * LDA; i += THREADS) A[i] = __float2half(0.f);
    // head weights: rows 0-3 fcs, 4-7 emb, 8-9 fcc
    for (int i = tid; i < 2560; i += THREADS) {
        int r = i >> 8, k = i & 255;
        float v = (r < 4) ? P.fcsW[r * 256 + k] : (r < 8) ? P.embW[(r - 4) * 256 + k]
                : P.fccW[(r - 8) * 256 + k];
        shw[i] = v;
    }
    if (tid < 4) sb[tid] = P.fcsB[tid];
    else if (tid < 8) sb[tid] = P.embB[tid - 4];
    else if (tid < 10) sb[tid] = P.fccB[tid - 8];
    __syncthreads();
    if (tid < 64) A[tid * LDA + 260] = __float2half(1.f);
    __syncthreads();

    run_phase(0, d_Bw[0][0], P.speed, P.out, b0, tid, A, aU, bs, shc, shw, sb, lg);
    run_phase(1, d_Bw[1][0], P.pos,   P.out, b0, tid, A, aU, bs, shc, shw, sb, lg);
    run_phase(2, d_Bw[2][0], P.speed, P.out, b0, tid, A, aU, bs, shc, shw, sb, lg);
    run_phase(3, d_Bw[3][0], P.pos,   P.out, b0, tid, A, aU, bs, shc, shw, sb, lg);
}

extern "C" void kernel_launch(void* const* d_in, const int* in_sizes, int n_in,
                              void* d_out, int out_size) {
    (void)in_sizes; (void)n_in; (void)out_size;

    Params P;
    P.speed = (const float*)d_in[0];
    P.pos   = (const float*)d_in[1];
    const int base[4] = {2, 6, 10, 14};   // sp_enc, po_enc, dec_speed, dec_cross
    for (int l = 0; l < 4; l++) {
        P.Wih[l] = (const float*)d_in[base[l] + 0];
        P.Whh[l] = (const float*)d_in[base[l] + 1];
        P.bih[l] = (const float*)d_in[base[l] + 2];
        P.bhh[l] = (const float*)d_in[base[l] + 3];
    }
    P.fcsW = (const float*)d_in[18]; P.fcsB = (const float*)d_in[19];
    P.fccW = (const float*)d_in[20]; P.fccB = (const float*)d_in[21];
    P.embW = (const float*)d_in[22]; P.embB = (const float*)d_in[23];
    P.out  = (float*)d_out;

    const int SMEM = 220736;
    cudaFuncSetAttribute(pv_main, cudaFuncAttributeMaxDynamicSharedMemorySize, SMEM);

    prep_kernel<<<560, 256>>>(P);             // 143360 chunks
    pv_main<<<BATCH / 64, THREADS, SMEM>>>(P);
}